// round 4
// baseline (speedup 1.0000x reference)
#include <cuda_runtime.h>
#include <math.h>
#include <stdint.h>

#define N_NODES  100000
#define N_EDGES  1600000
#define N_GRAPHS 1000
#define D        128

// ---------------- scratch (static device globals; no allocation) ----------------
__device__ float g_h    [(size_t)N_NODES * D];   // current activations
__device__ float g_hs   [(size_t)N_NODES * D];   // (h @ W) * dinv[row]
__device__ float g_dinv [N_NODES];
__device__ int   g_deg  [N_NODES];
__device__ int   g_rowptr[N_NODES + 1];
__device__ int   g_cursor[N_NODES];
__device__ int   g_esrc [N_EDGES];               // src ids sorted by dst (CSR)
__device__ float g_gmax [N_GRAPHS * D];

// ---------------- degree count ----------------
__global__ void k_count_deg(const int* __restrict__ dst) {
    int e = blockIdx.x * blockDim.x + threadIdx.x;
    if (e < N_EDGES) atomicAdd(&g_deg[dst[e]], 1);
}

// ---------------- single-block scan: rowptr / cursor / dinv from deg ----------------
__global__ void k_scan() {
    __shared__ int ssum[1024];
    int t = threadIdx.x;
    const int CH  = (N_NODES + 1023) / 1024;
    int beg = t * CH;
    int end = min(beg + CH, N_NODES);
    int s = 0;
    for (int i = beg; i < end; i++) s += g_deg[i];
    ssum[t] = s;
    __syncthreads();
    for (int off = 1; off < 1024; off <<= 1) {
        int v = (t >= off) ? ssum[t - off] : 0;
        __syncthreads();
        ssum[t] += v;
        __syncthreads();
    }
    int run = (t > 0) ? ssum[t - 1] : 0;
    for (int i = beg; i < end; i++) {
        int dg = g_deg[i];
        g_rowptr[i] = run;
        g_cursor[i] = run;
        g_dinv[i]   = rsqrtf((float)dg + 1.0f);
        run += dg;
    }
    if (t == 0) g_rowptr[N_NODES] = N_EDGES;
}

// ---------------- CSR fill ----------------
__global__ void k_fill_csr(const int* __restrict__ src, const int* __restrict__ dst) {
    int e = blockIdx.x * blockDim.x + threadIdx.x;
    if (e >= N_EDGES) return;
    int d   = __ldg(dst + e);
    int pos = atomicAdd(&g_cursor[d], 1);
    g_esrc[pos] = __ldg(src + e);
}

// ---------------- embedding lookup with max_norm=1 renorm ----------------
__global__ void k_embed(const int* __restrict__ x, const float* __restrict__ emb) {
    int t    = blockIdx.x * blockDim.x + threadIdx.x;
    int node = t >> 5;
    int lane = t & 31;
    if (node >= N_NODES) return;
    int v = __ldg(x + node);
    float4 e = __ldg((const float4*)(emb + (size_t)v * D) + lane);
    float ss = e.x * e.x + e.y * e.y + e.z * e.z + e.w * e.w;
    #pragma unroll
    for (int o = 16; o; o >>= 1) ss += __shfl_xor_sync(0xFFFFFFFFu, ss, o);
    float nrm   = sqrtf(ss);
    float scale = fminf(1.0f, 1.0f / fmaxf(nrm, 1e-7f));
    e.x *= scale; e.y *= scale; e.z *= scale; e.w *= scale;
    ((float4*)(g_h + (size_t)node * D))[lane] = e;
}

// ---------------- TF32 helpers ----------------
__device__ __forceinline__ uint32_t f2tf32(float x) {
    uint32_t r;
    asm("cvt.rna.tf32.f32 %0, %1;" : "=r"(r) : "f"(x));
    return r;
}
__device__ __forceinline__ void mma_tf32(float* c, const uint32_t a0, const uint32_t a1,
                                         const uint32_t a2, const uint32_t a3,
                                         const uint32_t b0, const uint32_t b1) {
    asm volatile(
        "mma.sync.aligned.m16n8k8.row.col.f32.tf32.tf32.f32 "
        "{%0,%1,%2,%3}, {%4,%5,%6,%7}, {%8,%9}, {%0,%1,%2,%3};"
        : "+f"(c[0]), "+f"(c[1]), "+f"(c[2]), "+f"(c[3])
        : "r"(a0), "r"(a1), "r"(a2), "r"(a3), "r"(b0), "r"(b1));
}

// ---------------- GEMM (3xTF32, staged hi/lo split): hs = (g_h @ W) * dinv[row] ----------------
// Block 128x128, 8 warps 4(M)x2(N), warp tile 32x64, mma m16n8k8, K chunks of 32.
#define A_STR 36
#define B_STR 136
#define OFF_AHI 0
#define OFF_ALO (128 * A_STR)
#define OFF_BHI (2 * 128 * A_STR)
#define OFF_BLO (2 * 128 * A_STR + 32 * B_STR)
#define SMEM_GEMM ((2 * 128 * A_STR + 2 * 32 * B_STR) * 4)

__global__ __launch_bounds__(256) void k_gemm(const float* __restrict__ W) {
    extern __shared__ uint32_t sm[];
    uint32_t* As_hi = sm + OFF_AHI;
    uint32_t* As_lo = sm + OFF_ALO;
    uint32_t* Bs_hi = sm + OFF_BHI;
    uint32_t* Bs_lo = sm + OFF_BLO;

    int tid  = threadIdx.x;
    int warp = tid >> 5, lane = tid & 31;
    int g = lane >> 2, t = lane & 3;
    int wm = warp >> 1;
    int wn = warp & 1;
    int rowBase = blockIdx.x * 128;
    int mBase = wm * 32;
    int nBase = wn * 64;

    float acc[2][8][4];
    #pragma unroll
    for (int i = 0; i < 2; i++)
        #pragma unroll
        for (int j = 0; j < 8; j++)
            #pragma unroll
            for (int k = 0; k < 4; k++) acc[i][j][k] = 0.0f;

    // per-thread staging coords
    const int ar = tid >> 1;                 // A row (128 rows, 2 thr/row)
    const int ac = (tid & 1) << 4;           // A col base: 0 or 16 (two float4 each)
    const int br = tid >> 5;                 // B row base (8 rows per pass, x4)
    const int bc = (tid & 31) << 2;          // B col

    float4 aReg[4], bReg[4];

    // prefetch chunk 0
    {
        const float* ap = g_h + (size_t)(rowBase + ar) * D + ac;
        bool ok = (rowBase + ar) < N_NODES;
        aReg[0] = ok ? __ldg((const float4*)(ap))     : make_float4(0,0,0,0);
        aReg[1] = ok ? __ldg((const float4*)(ap + 4)) : make_float4(0,0,0,0);
        aReg[2] = ok ? __ldg((const float4*)(ap + 8)) : make_float4(0,0,0,0);
        aReg[3] = ok ? __ldg((const float4*)(ap +12)) : make_float4(0,0,0,0);
        #pragma unroll
        for (int i = 0; i < 4; i++)
            bReg[i] = __ldg((const float4*)(W + (size_t)(br + i * 8) * D + bc));
    }

    for (int kc = 0; kc < 4; kc++) {
        // convert + store staged tiles
        #pragma unroll
        for (int i = 0; i < 4; i++) {
            float v[4] = {aReg[i].x, aReg[i].y, aReg[i].z, aReg[i].w};
            uint32_t hi[4], lo[4];
            #pragma unroll
            for (int c = 0; c < 4; c++) {
                hi[c] = f2tf32(v[c]);
                lo[c] = f2tf32(v[c] - __uint_as_float(hi[c]));
            }
            int off = ar * A_STR + ac + ((i & 1) << 2) + ((i >> 1) << 3);
            *(uint4*)&As_hi[off] = make_uint4(hi[0], hi[1], hi[2], hi[3]);
            *(uint4*)&As_lo[off] = make_uint4(lo[0], lo[1], lo[2], lo[3]);
        }
        #pragma unroll
        for (int i = 0; i < 4; i++) {
            float v[4] = {bReg[i].x, bReg[i].y, bReg[i].z, bReg[i].w};
            uint32_t hi[4], lo[4];
            #pragma unroll
            for (int c = 0; c < 4; c++) {
                hi[c] = f2tf32(v[c]);
                lo[c] = f2tf32(v[c] - __uint_as_float(hi[c]));
            }
            int off = (br + i * 8) * B_STR + bc;
            *(uint4*)&Bs_hi[off] = make_uint4(hi[0], hi[1], hi[2], hi[3]);
            *(uint4*)&Bs_lo[off] = make_uint4(lo[0], lo[1], lo[2], lo[3]);
        }
        __syncthreads();

        // prefetch next chunk while mma runs
        if (kc < 3) {
            int k0 = (kc + 1) * 32;
            const float* ap = g_h + (size_t)(rowBase + ar) * D + k0 + ac;
            bool ok = (rowBase + ar) < N_NODES;
            aReg[0] = ok ? __ldg((const float4*)(ap))     : make_float4(0,0,0,0);
            aReg[1] = ok ? __ldg((const float4*)(ap + 4)) : make_float4(0,0,0,0);
            aReg[2] = ok ? __ldg((const float4*)(ap + 8)) : make_float4(0,0,0,0);
            aReg[3] = ok ? __ldg((const float4*)(ap +12)) : make_float4(0,0,0,0);
            #pragma unroll
            for (int i = 0; i < 4; i++)
                bReg[i] = __ldg((const float4*)(W + (size_t)(k0 + br + i * 8) * D + bc));
        }

        #pragma unroll
        for (int ks = 0; ks < 32; ks += 8) {
            uint32_t ahi[2][4], alo[2][4];
            #pragma unroll
            for (int mt = 0; mt < 2; mt++) {
                int r0 = (mBase + mt * 16 + g) * A_STR + ks + t;
                int r1 = r0 + 8 * A_STR;
                ahi[mt][0] = As_hi[r0];     alo[mt][0] = As_lo[r0];
                ahi[mt][1] = As_hi[r1];     alo[mt][1] = As_lo[r1];
                ahi[mt][2] = As_hi[r0 + 4]; alo[mt][2] = As_lo[r0 + 4];
                ahi[mt][3] = As_hi[r1 + 4]; alo[mt][3] = As_lo[r1 + 4];
            }
            #pragma unroll
            for (int nt = 0; nt < 8; nt++) {
                int col = nBase + nt * 8 + g;
                int i0 = (ks + t) * B_STR + col;
                int i1 = i0 + 4 * B_STR;
                uint32_t bhi0 = Bs_hi[i0], bhi1 = Bs_hi[i1];
                uint32_t blo0 = Bs_lo[i0], blo1 = Bs_lo[i1];
                #pragma unroll
                for (int mt = 0; mt < 2; mt++) {
                    mma_tf32(acc[mt][nt], alo[mt][0], alo[mt][1], alo[mt][2], alo[mt][3], bhi0, bhi1);
                    mma_tf32(acc[mt][nt], ahi[mt][0], ahi[mt][1], ahi[mt][2], ahi[mt][3], blo0, blo1);
                    mma_tf32(acc[mt][nt], ahi[mt][0], ahi[mt][1], ahi[mt][2], ahi[mt][3], bhi0, bhi1);
                }
            }
        }
        __syncthreads();
    }

    // epilogue: scale by dinv[row], write hs
    #pragma unroll
    for (int mt = 0; mt < 2; mt++) {
        int r0 = rowBase + mBase + mt * 16 + g;
        int r1 = r0 + 8;
        float d0 = (r0 < N_NODES) ? g_dinv[r0] : 0.0f;
        float d1 = (r1 < N_NODES) ? g_dinv[r1] : 0.0f;
        #pragma unroll
        for (int nt = 0; nt < 8; nt++) {
            int col = nBase + nt * 8 + 2 * t;
            if (r0 < N_NODES) {
                float2 v = make_float2(acc[mt][nt][0] * d0, acc[mt][nt][1] * d0);
                *(float2*)(g_hs + (size_t)r0 * D + col) = v;
            }
            if (r1 < N_NODES) {
                float2 v = make_float2(acc[mt][nt][2] * d1, acc[mt][nt][3] * d1);
                *(float2*)(g_hs + (size_t)r1 * D + col) = v;
            }
        }
    }
}

// ---------------- CSR gather + fused epilogue (+ optional segmax), MLP=8 ----------------
template<bool LAST>
__global__ void k_gather(const float* __restrict__ b, const int* __restrict__ batch) {
    int t    = blockIdx.x * blockDim.x + threadIdx.x;
    int n    = t >> 5;
    int lane = t & 31;
    if (n >= N_NODES) return;

    int beg = __ldg(&g_rowptr[n]);
    int end = __ldg(&g_rowptr[n + 1]);

    float4 a0 = make_float4(0.f,0.f,0.f,0.f);
    float4 a1 = a0, a2 = a0, a3 = a0;

    int e = beg;
    for (; e + 8 <= end; e += 8) {
        int s[8];
        #pragma unroll
        for (int i = 0; i < 8; i++) s[i] = __ldg(&g_esrc[e + i]);
        float4 v[8];
        #pragma unroll
        for (int i = 0; i < 8; i++)
            v[i] = __ldg((const float4*)(g_hs + (size_t)s[i] * D) + lane);
        #pragma unroll
        for (int i = 0; i < 8; i += 4) {
            a0.x += v[i].x;   a0.y += v[i].y;   a0.z += v[i].z;   a0.w += v[i].w;
            a1.x += v[i+1].x; a1.y += v[i+1].y; a1.z += v[i+1].z; a1.w += v[i+1].w;
            a2.x += v[i+2].x; a2.y += v[i+2].y; a2.z += v[i+2].z; a2.w += v[i+2].w;
            a3.x += v[i+3].x; a3.y += v[i+3].y; a3.z += v[i+3].z; a3.w += v[i+3].w;
        }
    }
    for (; e + 4 <= end; e += 4) {
        int s0 = __ldg(&g_esrc[e]);
        int s1 = __ldg(&g_esrc[e + 1]);
        int s2 = __ldg(&g_esrc[e + 2]);
        int s3 = __ldg(&g_esrc[e + 3]);
        float4 v0 = __ldg((const float4*)(g_hs + (size_t)s0 * D) + lane);
        float4 v1 = __ldg((const float4*)(g_hs + (size_t)s1 * D) + lane);
        float4 v2 = __ldg((const float4*)(g_hs + (size_t)s2 * D) + lane);
        float4 v3 = __ldg((const float4*)(g_hs + (size_t)s3 * D) + lane);
        a0.x += v0.x; a0.y += v0.y; a0.z += v0.z; a0.w += v0.w;
        a1.x += v1.x; a1.y += v1.y; a1.z += v1.z; a1.w += v1.w;
        a2.x += v2.x; a2.y += v2.y; a2.z += v2.z; a2.w += v2.w;
        a3.x += v3.x; a3.y += v3.y; a3.z += v3.z; a3.w += v3.w;
    }
    for (; e < end; e++) {
        int s = __ldg(&g_esrc[e]);
        float4 v = __ldg((const float4*)(g_hs + (size_t)s * D) + lane);
        a0.x += v.x; a0.y += v.y; a0.z += v.z; a0.w += v.w;
    }

    float4 self = *((const float4*)(g_hs + (size_t)n * D) + lane);
    float4 acc;
    acc.x = (a0.x + a1.x) + (a2.x + a3.x) + self.x;
    acc.y = (a0.y + a1.y) + (a2.y + a3.y) + self.y;
    acc.z = (a0.z + a1.z) + (a2.z + a3.z) + self.z;
    acc.w = (a0.w + a1.w) + (a2.w + a3.w) + self.w;

    float  di = g_dinv[n];
    float4 bb = __ldg((const float4*)b + lane);
    float4 o;
    o.x = fmaxf(fmaf(acc.x, di, bb.x), 0.0f);
    o.y = fmaxf(fmaf(acc.y, di, bb.y), 0.0f);
    o.z = fmaxf(fmaf(acc.z, di, bb.z), 0.0f);
    o.w = fmaxf(fmaf(acc.w, di, bb.w), 0.0f);

    if (LAST) {
        int bg = __ldg(batch + n);
        int* q = (int*)(g_gmax + (size_t)bg * D + lane * 4);
        atomicMax(q + 0, __float_as_int(o.x));
        atomicMax(q + 1, __float_as_int(o.y));
        atomicMax(q + 2, __float_as_int(o.z));
        atomicMax(q + 3, __float_as_int(o.w));
    } else {
        *((float4*)(g_h + (size_t)n * D) + lane) = o;
    }
}

// ---------------- final readout ----------------
__global__ void k_final(const float* __restrict__ Wf, const float* __restrict__ bf,
                        float* __restrict__ out) {
    int t    = blockIdx.x * blockDim.x + threadIdx.x;
    int g    = t >> 5;
    int lane = t & 31;
    if (g >= N_GRAPHS) return;
    float4 v = *((const float4*)(g_gmax + (size_t)g * D) + lane);
    float4 w = __ldg((const float4*)Wf + lane);
    float s = v.x * w.x + v.y * w.y + v.z * w.z + v.w * w.w;
    #pragma unroll
    for (int o = 16; o; o >>= 1) s += __shfl_xor_sync(0xFFFFFFFFu, s, o);
    if (lane == 0) out[g] = s + bf[0];
}

// ---------------- launch ----------------
extern "C" void kernel_launch(void* const* d_in, const int* in_sizes, int n_in,
                              void* d_out, int out_size) {
    const int*   x     = (const int*)  d_in[0];
    const int*   ei    = (const int*)  d_in[1];
    const int*   batch = (const int*)  d_in[2];
    const float* emb   = (const float*)d_in[3];
    const float* Ws[3] = {(const float*)d_in[4], (const float*)d_in[6], (const float*)d_in[8]};
    const float* bs[3] = {(const float*)d_in[5], (const float*)d_in[7], (const float*)d_in[9]};
    const float* Wf    = (const float*)d_in[10];
    const float* bf    = (const float*)d_in[11];
    float* out = (float*)d_out;

    const int* src = ei;
    const int* dst = ei + N_EDGES;

    // persistent side stream + events (created once; no device allocation involved)
    static cudaStream_t s2 = [] {
        cudaStream_t s; cudaStreamCreateWithFlags(&s, cudaStreamNonBlocking); return s;
    }();
    static cudaEvent_t evFork = [] {
        cudaEvent_t e; cudaEventCreateWithFlags(&e, cudaEventDisableTiming); return e;
    }();
    static cudaEvent_t evScan = [] {
        cudaEvent_t e; cudaEventCreateWithFlags(&e, cudaEventDisableTiming); return e;
    }();
    static cudaEvent_t evCsr = [] {
        cudaEvent_t e; cudaEventCreateWithFlags(&e, cudaEventDisableTiming); return e;
    }();
    static bool smemSet = [] {
        cudaFuncSetAttribute(k_gemm, cudaFuncAttributeMaxDynamicSharedMemorySize, SMEM_GEMM);
        return true;
    }();
    (void)smemSet;

    void* degPtr  = nullptr; cudaGetSymbolAddress(&degPtr,  g_deg);
    void* gmaxPtr = nullptr; cudaGetSymbolAddress(&gmaxPtr, g_gmax);

    // fork side stream off the main (capture) stream
    cudaEventRecord(evFork, 0);
    cudaStreamWaitEvent(s2, evFork, 0);

    // side stream: CSR build chain
    cudaMemsetAsync(degPtr, 0, (size_t)N_NODES * sizeof(int), s2);
    k_count_deg<<<(N_EDGES + 255) / 256, 256, 0, s2>>>(dst);
    k_scan<<<1, 1024, 0, s2>>>();
    cudaEventRecord(evScan, s2);                 // dinv + rowptr ready
    k_fill_csr<<<(N_EDGES + 255) / 256, 256, 0, s2>>>(src, dst);
    cudaEventRecord(evCsr, s2);                  // esrc ready

    // main stream: gmax clear + embedding
    cudaMemsetAsync(gmaxPtr, 0, (size_t)N_GRAPHS * D * sizeof(float));
    k_embed<<<((size_t)N_NODES * 32 + 255) / 256, 256>>>(x, emb);

    const int gatherGrid = (N_NODES * 32 + 255) / 256;
    cudaStreamWaitEvent(0, evScan, 0);           // gemm epilogue needs dinv
    for (int l = 0; l < 3; l++) {
        k_gemm<<<(N_NODES + 127) / 128, 256, SMEM_GEMM>>>(Ws[l]);
        if (l == 0) cudaStreamWaitEvent(0, evCsr, 0);   // gather needs CSR
        if (l < 2) k_gather<false><<<gatherGrid, 256>>>(bs[l], batch);
        else       k_gather<true ><<<gatherGrid, 256>>>(bs[l], batch);
    }

    k_final<<<(N_GRAPHS * 32 + 255) / 256, 256>>>(Wf, bf, out);
}

// round 5
// speedup vs baseline: 1.0545x; 1.0545x over previous
#include <cuda_runtime.h>
#include <math.h>
#include <stdint.h>

#define N_NODES  100000
#define N_EDGES  1600000
#define N_GRAPHS 1000
#define D        128

#define EMB_BLOCKS   12500            // N_NODES*32/256
#define CNT_BLOCKS   6250             // N_EDGES/256
#define GEMM_BLOCKS  782              // ceil(N_NODES/128)
#define FILL_BLOCKS  6250             // N_EDGES/256

// ---------------- scratch (static device globals; no allocation) ----------------
__device__ float g_h    [(size_t)N_NODES * D];   // current activations
__device__ float g_hs   [(size_t)N_NODES * D];   // (h @ W) * dinv[row]
__device__ float g_dinv [N_NODES];
__device__ int   g_deg  [N_NODES];
__device__ int   g_rowptr[N_NODES + 1];
__device__ int   g_cursor[N_NODES];
__device__ int   g_esrc [N_EDGES];               // src ids sorted by dst (CSR)
__device__ float g_gmax [N_GRAPHS * D];

// ---------------- fused: embedding renorm + degree count (block-specialized) ----------------
__global__ void k_embed_count(const int* __restrict__ x, const float* __restrict__ emb,
                              const int* __restrict__ dst) {
    if (blockIdx.x < EMB_BLOCKS) {
        int t    = blockIdx.x * blockDim.x + threadIdx.x;
        int node = t >> 5;
        int lane = t & 31;
        if (node >= N_NODES) return;
        int v = __ldg(x + node);
        float4 e = __ldg((const float4*)(emb + (size_t)v * D) + lane);
        float ss = e.x * e.x + e.y * e.y + e.z * e.z + e.w * e.w;
        #pragma unroll
        for (int o = 16; o; o >>= 1) ss += __shfl_xor_sync(0xFFFFFFFFu, ss, o);
        float nrm   = sqrtf(ss);
        float scale = fminf(1.0f, 1.0f / fmaxf(nrm, 1e-7f));
        e.x *= scale; e.y *= scale; e.z *= scale; e.w *= scale;
        ((float4*)(g_h + (size_t)node * D))[lane] = e;
    } else {
        int e = (blockIdx.x - EMB_BLOCKS) * blockDim.x + threadIdx.x;
        if (e < N_EDGES) atomicAdd(&g_deg[__ldg(dst + e)], 1);
    }
}

// ---------------- single-block scan: rowptr / cursor / dinv from deg ----------------
__global__ void k_scan() {
    __shared__ int ssum[1024];
    int t = threadIdx.x;
    const int CH  = (N_NODES + 1023) / 1024;
    int beg = t * CH;
    int end = min(beg + CH, N_NODES);
    int s = 0;
    for (int i = beg; i < end; i++) s += g_deg[i];
    ssum[t] = s;
    __syncthreads();
    for (int off = 1; off < 1024; off <<= 1) {
        int v = (t >= off) ? ssum[t - off] : 0;
        __syncthreads();
        ssum[t] += v;
        __syncthreads();
    }
    int run = (t > 0) ? ssum[t - 1] : 0;
    for (int i = beg; i < end; i++) {
        int dg = g_deg[i];
        g_rowptr[i] = run;
        g_cursor[i] = run;
        g_dinv[i]   = rsqrtf((float)dg + 1.0f);
        run += dg;
    }
    if (t == 0) g_rowptr[N_NODES] = N_EDGES;
}

// ---------------- TF32 helpers ----------------
__device__ __forceinline__ uint32_t f2tf32(float x) {
    uint32_t r;
    asm("cvt.rna.tf32.f32 %0, %1;" : "=r"(r) : "f"(x));
    return r;
}
__device__ __forceinline__ void split_tf32(float x, uint32_t& hi, uint32_t& lo) {
    hi = f2tf32(x);
    lo = f2tf32(x - __uint_as_float(hi));
}
__device__ __forceinline__ void mma_tf32(float* c, const uint32_t a0, const uint32_t a1,
                                         const uint32_t a2, const uint32_t a3,
                                         const uint32_t b0, const uint32_t b1) {
    asm volatile(
        "mma.sync.aligned.m16n8k8.row.col.f32.tf32.tf32.f32 "
        "{%0,%1,%2,%3}, {%4,%5,%6,%7}, {%8,%9}, {%0,%1,%2,%3};"
        : "+f"(c[0]), "+f"(c[1]), "+f"(c[2]), "+f"(c[3])
        : "r"(a0), "r"(a1), "r"(a2), "r"(a3), "r"(b0), "r"(b1));
}

// ---------------- GEMM (3xTF32, R3 version): hs = (g_h @ W) * dinv[row] ----------------
// Block 128x128, 8 warps 4(M)x2(N), warp tile 32x64, mma m16n8k8.
// FILL=true: extra trailing blocks perform the CSR bucket fill (overlapped).
#define A_STRIDE 36
#define B_STRIDE 136
template<bool FILL>
__global__ __launch_bounds__(256) void k_gemm(const float* __restrict__ W,
                                              const int* __restrict__ src,
                                              const int* __restrict__ dst) {
    __shared__ float As[128][A_STRIDE];
    __shared__ float Bs[32][B_STRIDE];

    if (FILL && blockIdx.x >= GEMM_BLOCKS) {
        int e = (blockIdx.x - GEMM_BLOCKS) * blockDim.x + threadIdx.x;
        if (e < N_EDGES) {
            int d   = __ldg(dst + e);
            int pos = atomicAdd(&g_cursor[d], 1);
            g_esrc[pos] = __ldg(src + e);
        }
        return;
    }

    int tid  = threadIdx.x;
    int warp = tid >> 5, lane = tid & 31;
    int g = lane >> 2, t = lane & 3;
    int wm = warp >> 1;            // 0..3
    int wn = warp & 1;             // 0..1
    int rowBase = blockIdx.x * 128;
    int mBase = wm * 32;
    int nBase = wn * 64;

    float acc[2][8][4];
    #pragma unroll
    for (int i = 0; i < 2; i++)
        #pragma unroll
        for (int j = 0; j < 8; j++)
            #pragma unroll
            for (int k = 0; k < 4; k++) acc[i][j][k] = 0.0f;

    for (int k0 = 0; k0 < D; k0 += 32) {
        #pragma unroll
        for (int i = 0; i < 4; i++) {
            int idx = tid + i * 256;
            int r   = idx >> 3;
            int c   = (idx & 7) << 2;
            int gr  = rowBase + r;
            float4 v = (gr < N_NODES)
                ? __ldg((const float4*)(g_h + (size_t)gr * D + k0 + c))
                : make_float4(0.f, 0.f, 0.f, 0.f);
            *(float4*)&As[r][c] = v;
        }
        #pragma unroll
        for (int i = 0; i < 4; i++) {
            int idx = tid + i * 256;
            int r   = idx >> 5;
            int c   = (idx & 31) << 2;
            float4 v = __ldg((const float4*)(W + (size_t)(k0 + r) * D + c));
            *(float4*)&Bs[r][c] = v;
        }
        __syncthreads();

        #pragma unroll
        for (int ks = 0; ks < 32; ks += 8) {
            uint32_t ahi[2][4], alo[2][4];
            #pragma unroll
            for (int mt = 0; mt < 2; mt++) {
                int r0 = mBase + mt * 16 + g;
                int r1 = r0 + 8;
                float a0 = As[r0][ks + t];
                float a1 = As[r1][ks + t];
                float a2 = As[r0][ks + t + 4];
                float a3 = As[r1][ks + t + 4];
                split_tf32(a0, ahi[mt][0], alo[mt][0]);
                split_tf32(a1, ahi[mt][1], alo[mt][1]);
                split_tf32(a2, ahi[mt][2], alo[mt][2]);
                split_tf32(a3, ahi[mt][3], alo[mt][3]);
            }
            #pragma unroll
            for (int nt = 0; nt < 8; nt++) {
                int col = nBase + nt * 8 + g;
                float b0f = Bs[ks + t][col];
                float b1f = Bs[ks + t + 4][col];
                uint32_t bhi0, blo0, bhi1, blo1;
                split_tf32(b0f, bhi0, blo0);
                split_tf32(b1f, bhi1, blo1);
                #pragma unroll
                for (int mt = 0; mt < 2; mt++) {
                    mma_tf32(acc[mt][nt], alo[mt][0], alo[mt][1], alo[mt][2], alo[mt][3], bhi0, bhi1);
                    mma_tf32(acc[mt][nt], ahi[mt][0], ahi[mt][1], ahi[mt][2], ahi[mt][3], blo0, blo1);
                    mma_tf32(acc[mt][nt], ahi[mt][0], ahi[mt][1], ahi[mt][2], ahi[mt][3], bhi0, bhi1);
                }
            }
        }
        __syncthreads();
    }

    #pragma unroll
    for (int mt = 0; mt < 2; mt++) {
        int r0 = rowBase + mBase + mt * 16 + g;
        int r1 = r0 + 8;
        float d0 = (r0 < N_NODES) ? g_dinv[r0] : 0.0f;
        float d1 = (r1 < N_NODES) ? g_dinv[r1] : 0.0f;
        #pragma unroll
        for (int nt = 0; nt < 8; nt++) {
            int col = nBase + nt * 8 + 2 * t;
            if (r0 < N_NODES) {
                float2 v = make_float2(acc[mt][nt][0] * d0, acc[mt][nt][1] * d0);
                *(float2*)(g_hs + (size_t)r0 * D + col) = v;
            }
            if (r1 < N_NODES) {
                float2 v = make_float2(acc[mt][nt][2] * d1, acc[mt][nt][3] * d1);
                *(float2*)(g_hs + (size_t)r1 * D + col) = v;
            }
        }
    }
}

// ---------------- CSR gather + fused epilogue (+ optional segmax), MLP=8 ----------------
template<bool LAST>
__global__ void k_gather(const float* __restrict__ b, const int* __restrict__ batch) {
    int t    = blockIdx.x * blockDim.x + threadIdx.x;
    int n    = t >> 5;
    int lane = t & 31;
    if (n >= N_NODES) return;

    int beg = __ldg(&g_rowptr[n]);
    int end = __ldg(&g_rowptr[n + 1]);

    float4 a0 = make_float4(0.f,0.f,0.f,0.f);
    float4 a1 = a0, a2 = a0, a3 = a0;

    int e = beg;
    for (; e + 8 <= end; e += 8) {
        int s[8];
        #pragma unroll
        for (int i = 0; i < 8; i++) s[i] = __ldg(&g_esrc[e + i]);
        float4 v[8];
        #pragma unroll
        for (int i = 0; i < 8; i++)
            v[i] = __ldg((const float4*)(g_hs + (size_t)s[i] * D) + lane);
        #pragma unroll
        for (int i = 0; i < 8; i += 4) {
            a0.x += v[i].x;   a0.y += v[i].y;   a0.z += v[i].z;   a0.w += v[i].w;
            a1.x += v[i+1].x; a1.y += v[i+1].y; a1.z += v[i+1].z; a1.w += v[i+1].w;
            a2.x += v[i+2].x; a2.y += v[i+2].y; a2.z += v[i+2].z; a2.w += v[i+2].w;
            a3.x += v[i+3].x; a3.y += v[i+3].y; a3.z += v[i+3].z; a3.w += v[i+3].w;
        }
    }
    for (; e + 4 <= end; e += 4) {
        int s0 = __ldg(&g_esrc[e]);
        int s1 = __ldg(&g_esrc[e + 1]);
        int s2 = __ldg(&g_esrc[e + 2]);
        int s3 = __ldg(&g_esrc[e + 3]);
        float4 v0 = __ldg((const float4*)(g_hs + (size_t)s0 * D) + lane);
        float4 v1 = __ldg((const float4*)(g_hs + (size_t)s1 * D) + lane);
        float4 v2 = __ldg((const float4*)(g_hs + (size_t)s2 * D) + lane);
        float4 v3 = __ldg((const float4*)(g_hs + (size_t)s3 * D) + lane);
        a0.x += v0.x; a0.y += v0.y; a0.z += v0.z; a0.w += v0.w;
        a1.x += v1.x; a1.y += v1.y; a1.z += v1.z; a1.w += v1.w;
        a2.x += v2.x; a2.y += v2.y; a2.z += v2.z; a2.w += v2.w;
        a3.x += v3.x; a3.y += v3.y; a3.z += v3.z; a3.w += v3.w;
    }
    for (; e < end; e++) {
        int s = __ldg(&g_esrc[e]);
        float4 v = __ldg((const float4*)(g_hs + (size_t)s * D) + lane);
        a0.x += v.x; a0.y += v.y; a0.z += v.z; a0.w += v.w;
    }

    float4 self = *((const float4*)(g_hs + (size_t)n * D) + lane);
    float4 acc;
    acc.x = (a0.x + a1.x) + (a2.x + a3.x) + self.x;
    acc.y = (a0.y + a1.y) + (a2.y + a3.y) + self.y;
    acc.z = (a0.z + a1.z) + (a2.z + a3.z) + self.z;
    acc.w = (a0.w + a1.w) + (a2.w + a3.w) + self.w;

    float  di = g_dinv[n];
    float4 bb = __ldg((const float4*)b + lane);
    float4 o;
    o.x = fmaxf(fmaf(acc.x, di, bb.x), 0.0f);
    o.y = fmaxf(fmaf(acc.y, di, bb.y), 0.0f);
    o.z = fmaxf(fmaf(acc.z, di, bb.z), 0.0f);
    o.w = fmaxf(fmaf(acc.w, di, bb.w), 0.0f);

    if (LAST) {
        int bg = __ldg(batch + n);
        int* q = (int*)(g_gmax + (size_t)bg * D + lane * 4);
        atomicMax(q + 0, __float_as_int(o.x));
        atomicMax(q + 1, __float_as_int(o.y));
        atomicMax(q + 2, __float_as_int(o.z));
        atomicMax(q + 3, __float_as_int(o.w));
    } else {
        *((float4*)(g_h + (size_t)n * D) + lane) = o;
    }
}

// ---------------- final readout ----------------
__global__ void k_final(const float* __restrict__ Wf, const float* __restrict__ bf,
                        float* __restrict__ out) {
    int t    = blockIdx.x * blockDim.x + threadIdx.x;
    int g    = t >> 5;
    int lane = t & 31;
    if (g >= N_GRAPHS) return;
    float4 v = *((const float4*)(g_gmax + (size_t)g * D) + lane);
    float4 w = __ldg((const float4*)Wf + lane);
    float s = v.x * w.x + v.y * w.y + v.z * w.z + v.w * w.w;
    #pragma unroll
    for (int o = 16; o; o >>= 1) s += __shfl_xor_sync(0xFFFFFFFFu, s, o);
    if (lane == 0) out[g] = s + bf[0];
}

// ---------------- launch (single stream, R3 ordering + fusions) ----------------
extern "C" void kernel_launch(void* const* d_in, const int* in_sizes, int n_in,
                              void* d_out, int out_size) {
    const int*   x     = (const int*)  d_in[0];
    const int*   ei    = (const int*)  d_in[1];
    const int*   batch = (const int*)  d_in[2];
    const float* emb   = (const float*)d_in[3];
    const float* Ws[3] = {(const float*)d_in[4], (const float*)d_in[6], (const float*)d_in[8]};
    const float* bs[3] = {(const float*)d_in[5], (const float*)d_in[7], (const float*)d_in[9]};
    const float* Wf    = (const float*)d_in[10];
    const float* bf    = (const float*)d_in[11];
    float* out = (float*)d_out;

    const int* src = ei;
    const int* dst = ei + N_EDGES;

    void* degPtr  = nullptr; cudaGetSymbolAddress(&degPtr,  g_deg);
    void* gmaxPtr = nullptr; cudaGetSymbolAddress(&gmaxPtr, g_gmax);
    cudaMemsetAsync(degPtr,  0, (size_t)N_NODES  * sizeof(int));
    cudaMemsetAsync(gmaxPtr, 0, (size_t)N_GRAPHS * D * sizeof(float));

    // fused embed + degree count
    k_embed_count<<<EMB_BLOCKS + CNT_BLOCKS, 256>>>(x, emb, dst);
    k_scan<<<1, 1024>>>();

    const int gatherGrid = (N_NODES * 32 + 255) / 256;
    // layer 0: GEMM fused with CSR fill (fill hides under GEMM)
    k_gemm<true><<<GEMM_BLOCKS + FILL_BLOCKS, 256>>>(Ws[0], src, dst);
    k_gather<false><<<gatherGrid, 256>>>(bs[0], batch);
    // layers 1,2
    k_gemm<false><<<GEMM_BLOCKS, 256>>>(Ws[1], src, dst);
    k_gather<false><<<gatherGrid, 256>>>(bs[1], batch);
    k_gemm<false><<<GEMM_BLOCKS, 256>>>(Ws[2], src, dst);
    k_gather<true ><<<gatherGrid, 256>>>(bs[2], batch);

    k_final<<<(N_GRAPHS * 32 + 255) / 256, 256>>>(Wf, bf, out);
}